// round 1
// baseline (speedup 1.0000x reference)
#include <cuda_runtime.h>
#include <cmath>
#include <stdint.h>

#define NLEV  16
#define TSIZE (1u << 19)
#define HID   64
#define ENC   32
#define PRIME2 2654435761u
#define PRIME3 805459861u

typedef unsigned long long u64;

struct LevelParams {
    float    resf[NLEV];
    unsigned s1[NLEV];     // res+1           (dense stride y)
    unsigned s2[NLEV];     // (res+1)^2       (dense stride z)
    int      dense[NLEV];
};

__device__ __forceinline__ u64 pk2(float a, float b) {
    u64 r; asm("mov.b64 %0, {%1,%2};" : "=l"(r) : "f"(a), "f"(b)); return r;
}
__device__ __forceinline__ void upk2(u64 v, float& a, float& b) {
    asm("mov.b64 {%0,%1}, %2;" : "=f"(a), "=f"(b) : "l"(v));
}
// Blackwell packed fp32 FMA: 2 FMAs per instruction (FFMA2 in SASS).
__device__ __forceinline__ u64 ffma2(u64 a, u64 b, u64 c) {
    u64 d; asm("fma.rn.f32x2 %0, %1, %2, %3;" : "=l"(d) : "l"(a), "l"(b), "l"(c)); return d;
}

__global__ void __launch_bounds__(128) sdf_fused(
    const float* __restrict__ x,
    const float* __restrict__ tables,
    const float* __restrict__ W0,
    const float* __restrict__ W1,
    const float* __restrict__ W2,
    float* __restrict__ out,
    int npts, LevelParams lp)
{
    __shared__ __align__(16) float sW0[ENC * HID];   //  8 KB
    __shared__ __align__(16) float sW1[HID * HID];   // 16 KB
    __shared__ __align__(16) float sW2[HID];         // 256 B
    __shared__ __align__(16) float sH[HID * 128];    // 32 KB hidden, transposed [i][tid]

    {
        int t = threadIdx.x;
        float4*       s0 = (float4*)sW0;  const float4* g0 = (const float4*)W0;
        for (int i = t; i < ENC * HID / 4; i += blockDim.x) s0[i] = g0[i];
        float4*       s1 = (float4*)sW1;  const float4* g1 = (const float4*)W1;
        for (int i = t; i < HID * HID / 4; i += blockDim.x) s1[i] = g1[i];
        if (t < HID / 4) ((float4*)sW2)[t] = ((const float4*)W2)[t];
    }
    __syncthreads();

    const int pt = blockIdx.x * blockDim.x + threadIdx.x;
    if (pt >= npts) return;

    const float x0 = (x[3 * pt + 0] + 1.0f) * 0.5f;
    const float y0 = (x[3 * pt + 1] + 1.0f) * 0.5f;
    const float z0 = (x[3 * pt + 2] + 1.0f) * 0.5f;

    // layer-0 accumulators: 64 floats as 32 packed f32x2
    u64 acc[HID / 2];
#pragma unroll
    for (int j = 0; j < HID / 2; j++) acc[j] = 0ull;

    for (int l = 0; l < NLEV; l++) {
        const float rf = lp.resf[l];
        const float px = x0 * rf, py = y0 * rf, pz = z0 * rf;
        const float fpx = floorf(px), fpy = floorf(py), fpz = floorf(pz);
        const float fx = px - fpx, fy = py - fpy, fz = pz - fpz;
        const unsigned cx = (unsigned)fpx, cy = (unsigned)fpy, cz = (unsigned)fpz;

        const float2* __restrict__ tab = ((const float2*)tables) + (size_t)l * TSIZE;

        unsigned idx[8];
        if (lp.dense[l]) {
            const unsigned s1 = lp.s1[l], s2 = lp.s2[l];
            const unsigned ax0 = cx,        ax1 = cx + 1u;
            const unsigned ay0 = cy * s1,   ay1 = ay0 + s1;
            const unsigned az0 = cz * s2,   az1 = az0 + s2;
            idx[0] = ax0 + ay0 + az0;  idx[1] = ax0 + ay0 + az1;
            idx[2] = ax0 + ay1 + az0;  idx[3] = ax0 + ay1 + az1;
            idx[4] = ax1 + ay0 + az0;  idx[5] = ax1 + ay0 + az1;
            idx[6] = ax1 + ay1 + az0;  idx[7] = ax1 + ay1 + az1;
        } else {
            const unsigned ax0 = cx,            ax1 = cx + 1u;
            const unsigned ay0 = cy * PRIME2,   ay1 = ay0 + PRIME2;
            const unsigned az0 = cz * PRIME3,   az1 = az0 + PRIME3;
            const unsigned m = TSIZE - 1u;
            idx[0] = (ax0 ^ ay0 ^ az0) & m;  idx[1] = (ax0 ^ ay0 ^ az1) & m;
            idx[2] = (ax0 ^ ay1 ^ az0) & m;  idx[3] = (ax0 ^ ay1 ^ az1) & m;
            idx[4] = (ax1 ^ ay0 ^ az0) & m;  idx[5] = (ax1 ^ ay0 ^ az1) & m;
            idx[6] = (ax1 ^ ay1 ^ az0) & m;  idx[7] = (ax1 ^ ay1 ^ az1) & m;
        }

        float2 f[8];
#pragma unroll
        for (int c = 0; c < 8; c++) f[c] = __ldg(&tab[idx[c]]);

        const float wx[2] = {1.0f - fx, fx};
        const float wy[2] = {1.0f - fy, fy};
        const float wz[2] = {1.0f - fz, fz};
        float e0 = 0.0f, e1 = 0.0f;
#pragma unroll
        for (int ci = 0; ci < 2; ci++)
#pragma unroll
            for (int cj = 0; cj < 2; cj++)
#pragma unroll
                for (int ck = 0; ck < 2; ck++) {
                    const int c = ci * 4 + cj * 2 + ck;
                    const float w = wx[ci] * wy[cj] * wz[ck];
                    e0 = fmaf(w, f[c].x, e0);
                    e1 = fmaf(w, f[c].y, e1);
                }

        // stream this level's 2 features through layer 0 (rows 2l, 2l+1 of W0)
        const u64 a0 = pk2(e0, e0), a1 = pk2(e1, e1);
        const ulonglong2* __restrict__ r0 = (const ulonglong2*)&sW0[(2 * l) * HID];
        const ulonglong2* __restrict__ r1 = (const ulonglong2*)&sW0[(2 * l + 1) * HID];
#pragma unroll
        for (int j = 0; j < HID / 4; j++) {
            const ulonglong2 v0 = r0[j];
            const ulonglong2 v1 = r1[j];
            acc[2 * j]     = ffma2(a1, v1.x, ffma2(a0, v0.x, acc[2 * j]));
            acc[2 * j + 1] = ffma2(a1, v1.y, ffma2(a0, v0.y, acc[2 * j + 1]));
        }
    }

    // ReLU -> hidden to smem (transposed, conflict-free), reset accumulators
    {
        const int t = threadIdx.x;
#pragma unroll
        for (int j = 0; j < HID / 2; j++) {
            float a, b; upk2(acc[j], a, b);
            sH[(2 * j) * 128 + t]     = fmaxf(a, 0.0f);
            sH[(2 * j + 1) * 128 + t] = fmaxf(b, 0.0f);
            acc[j] = 0ull;
        }
    }

    // layer 1: 64x64
    {
        const int t = threadIdx.x;
#pragma unroll 8
        for (int i = 0; i < HID; i++) {
            const float hi = sH[i * 128 + t];
            const u64 ai = pk2(hi, hi);
            const ulonglong2* __restrict__ r = (const ulonglong2*)&sW1[i * HID];
#pragma unroll
            for (int j = 0; j < HID / 4; j++) {
                const ulonglong2 v = r[j];
                acc[2 * j]     = ffma2(ai, v.x, acc[2 * j]);
                acc[2 * j + 1] = ffma2(ai, v.y, acc[2 * j + 1]);
            }
        }
    }

    // ReLU + layer 2 (64 -> 1)
    float res = 0.0f;
#pragma unroll
    for (int j = 0; j < HID / 2; j++) {
        float a, b; upk2(acc[j], a, b);
        res = fmaf(fmaxf(a, 0.0f), sW2[2 * j], res);
        res = fmaf(fmaxf(b, 0.0f), sW2[2 * j + 1], res);
    }
    out[pt] = res;
}

static LevelParams make_params() {
    LevelParams lp;
    for (int l = 0; l < NLEV; l++) {
        // match numpy: floor(16 * 1.3819**l) in float64
        const double r = floor(16.0 * pow(1.3819, (double)l));
        const int res = (int)r;
        lp.resf[l] = (float)res;
        const unsigned s1 = (unsigned)(res + 1);
        lp.s1[l] = s1;
        lp.s2[l] = s1 * s1;
        const double r1 = (double)(res + 1);
        lp.dense[l] = (r1 * r1 * r1 <= (double)TSIZE) ? 1 : 0;
    }
    return lp;
}

extern "C" void kernel_launch(void* const* d_in, const int* in_sizes, int n_in,
                              void* d_out, int out_size) {
    const float* x      = (const float*)d_in[0];
    const float* tables = (const float*)d_in[1];
    const float* W0     = (const float*)d_in[2];
    const float* W1     = (const float*)d_in[3];
    const float* W2     = (const float*)d_in[4];
    float* out = (float*)d_out;

    const int npts = out_size;  // [N,1] SDF values
    LevelParams lp = make_params();

    const int block = 128;
    const int grid = (npts + block - 1) / block;
    sdf_fused<<<grid, block>>>(x, tables, W0, W1, W2, out, npts, lp);
}

// round 2
// speedup vs baseline: 1.0875x; 1.0875x over previous
#include <cuda_runtime.h>
#include <cmath>
#include <stdint.h>

#define NLEV   16
#define NDENSE 5
#define TSIZE  (1u << 19)
#define HID    64
#define ENC    32
#define P2     2654435761u
#define P3     805459861u

typedef unsigned long long u64;

// Padded x-pair tables for the dense levels: Q[i] = (tab[i], tab[i+1]).
// Sized for sum over dense levels of (res+1)^3+(res+1)^2+(res+1)+2  (~339K).
#define QCAP 339072
__device__ float4 g_Q[QCAP];

struct LevelParams {
    float    resf[NLEV];
    unsigned s1[NLEV];        // res+1
    unsigned s2[NLEV];        // (res+1)^2
    unsigned qoff[NDENSE];    // offset of level's pair-table inside g_Q
    unsigned qcnt[NDENSE];    // entries in level's pair-table
};

__device__ __forceinline__ u64 pk2(float a, float b) {
    u64 r; asm("mov.b64 %0, {%1,%2};" : "=l"(r) : "f"(a), "f"(b)); return r;
}
__device__ __forceinline__ void upk2(u64 v, float& a, float& b) {
    asm("mov.b64 {%0,%1}, %2;" : "=f"(a), "=f"(b) : "l"(v));
}
// Blackwell packed fp32 FMA (FFMA2), only reachable via PTX.
__device__ __forceinline__ u64 ffma2(u64 a, u64 b, u64 c) {
    u64 d; asm("fma.rn.f32x2 %0, %1, %2, %3;" : "=l"(d) : "l"(a), "l"(b), "l"(c)); return d;
}

// ---------- prologue: build dense pair tables ----------
__global__ void build_q(const float2* __restrict__ tables, LevelParams lp, unsigned total) {
    unsigned i = blockIdx.x * blockDim.x + threadIdx.x;
    if (i >= total) return;
    int l = 0; unsigned base = 0;
#pragma unroll
    for (int k = 0; k < NDENSE; k++) {
        unsigned o = lp.qoff[k];
        if (i >= o && i < o + lp.qcnt[k]) { l = k; base = o; }
    }
    unsigned j = i - base;
    const float2* __restrict__ tab = tables + (size_t)l * TSIZE;
    float2 a = __ldg(&tab[j]);
    float2 b = __ldg(&tab[j + 1]);
    g_Q[i] = make_float4(a.x, a.y, b.x, b.y);
}

// ---------- shared epilogue for one level: trilinear + stream through layer 0 ----------
__device__ __forceinline__ void level_accumulate(
    int l, const float2 f0[4], const float2 f1[4],
    float fx, float fy, float fz, u64 acc[HID / 2], const float* sW0)
{
    const float gy = 1.0f - fy, gz = 1.0f - fz, gx = 1.0f - fx;
    float wyz[4];
    wyz[0] = gy * gz;  wyz[1] = gy * fz;  wyz[2] = fy * gz;  wyz[3] = fy * fz;

    float e0 = 0.0f, e1 = 0.0f;
#pragma unroll
    for (int j = 0; j < 4; j++) {
        const float w0 = wyz[j] * gx;
        const float w1 = wyz[j] * fx;
        e0 = fmaf(w0, f0[j].x, fmaf(w1, f1[j].x, e0));
        e1 = fmaf(w0, f0[j].y, fmaf(w1, f1[j].y, e1));
    }

    const u64 a0 = pk2(e0, e0), a1 = pk2(e1, e1);
    const ulonglong2* __restrict__ r0 = (const ulonglong2*)&sW0[(2 * l) * HID];
    const ulonglong2* __restrict__ r1 = (const ulonglong2*)&sW0[(2 * l + 1) * HID];
#pragma unroll
    for (int j = 0; j < HID / 4; j++) {
        const ulonglong2 v0 = r0[j];
        const ulonglong2 v1 = r1[j];
        acc[2 * j]     = ffma2(a1, v1.x, ffma2(a0, v0.x, acc[2 * j]));
        acc[2 * j + 1] = ffma2(a1, v1.y, ffma2(a0, v0.y, acc[2 * j + 1]));
    }
}

__global__ void __launch_bounds__(128) sdf_fused(
    const float* __restrict__ x,
    const float* __restrict__ tables,
    const float* __restrict__ W0,
    const float* __restrict__ W1,
    const float* __restrict__ W2,
    float* __restrict__ out,
    int npts, LevelParams lp)
{
    __shared__ __align__(16) float sW0[ENC * HID];   //  8 KB
    __shared__ __align__(16) float sW1[HID * HID];   // 16 KB
    __shared__ __align__(16) float sW2[HID];         // 256 B
    __shared__ __align__(16) float sH[HID * 128];    // 32 KB hidden, transposed [i][tid]

    {
        int t = threadIdx.x;
        float4*       s0 = (float4*)sW0;  const float4* g0 = (const float4*)W0;
        for (int i = t; i < ENC * HID / 4; i += blockDim.x) s0[i] = g0[i];
        float4*       s1 = (float4*)sW1;  const float4* g1 = (const float4*)W1;
        for (int i = t; i < HID * HID / 4; i += blockDim.x) s1[i] = g1[i];
        if (t < HID / 4) ((float4*)sW2)[t] = ((const float4*)W2)[t];
    }
    __syncthreads();

    const int pt = blockIdx.x * blockDim.x + threadIdx.x;
    if (pt >= npts) return;

    const float x0 = (x[3 * pt + 0] + 1.0f) * 0.5f;
    const float y0 = (x[3 * pt + 1] + 1.0f) * 0.5f;
    const float z0 = (x[3 * pt + 2] + 1.0f) * 0.5f;

    u64 acc[HID / 2];
#pragma unroll
    for (int j = 0; j < HID / 2; j++) acc[j] = 0ull;

    // ---- dense levels: one LDG.128 per x-pair from g_Q ----
#pragma unroll
    for (int l = 0; l < NDENSE; l++) {
        const float rf = lp.resf[l];
        const float px = x0 * rf, py = y0 * rf, pz = z0 * rf;
        const float fpx = floorf(px), fpy = floorf(py), fpz = floorf(pz);
        const float fx = px - fpx, fy = py - fpy, fz = pz - fpz;
        const unsigned cx = (unsigned)fpx, cy = (unsigned)fpy, cz = (unsigned)fpz;

        const unsigned s1 = lp.s1[l], s2 = lp.s2[l];
        const unsigned ay0 = cy * s1, az0 = cz * s2;
        const float4* __restrict__ Q = g_Q + lp.qoff[l];

        unsigned b[4];
        b[0] = cx + ay0 + az0;
        b[1] = b[0] + s2;
        b[2] = b[0] + s1;
        b[3] = b[2] + s2;

        float2 f0[4], f1[4];
#pragma unroll
        for (int j = 0; j < 4; j++) {
            const float4 q = __ldg(&Q[b[j]]);
            f0[j] = make_float2(q.x, q.y);
            f1[j] = make_float2(q.z, q.w);
        }
        level_accumulate(l, f0, f1, fx, fy, fz, acc, sW0);
    }

    // ---- hashed levels: pair via h(x+1)=h(x)^1 when cx is even ----
#pragma unroll 1
    for (int l = NDENSE; l < NLEV; l++) {
        const float rf = lp.resf[l];
        const float px = x0 * rf, py = y0 * rf, pz = z0 * rf;
        const float fpx = floorf(px), fpy = floorf(py), fpz = floorf(pz);
        const float fx = px - fpx, fy = py - fpy, fz = pz - fpz;
        const unsigned cx = (unsigned)fpx, cy = (unsigned)fpy, cz = (unsigned)fpz;

        const float2* __restrict__ tab2 = ((const float2*)tables) + (size_t)l * TSIZE;
        const float4* __restrict__ tab4 = (const float4*)tab2;
        const unsigned m = TSIZE - 1u;

        const unsigned ay0 = cy * P2, az0 = cz * P3;
        unsigned s[4];
        s[0] = ay0 ^ az0;
        s[1] = ay0 ^ (az0 + P3);
        s[2] = (ay0 + P2) ^ az0;
        s[3] = (ay0 + P2) ^ (az0 + P3);

        float2 f0[4], f1[4];
        if ((cx & 1u) == 0u) {
#pragma unroll
            for (int j = 0; j < 4; j++) {
                const unsigned i0 = (cx ^ s[j]) & m;
                const float4 q = __ldg(&tab4[i0 >> 1]);
                const bool hi = (i0 & 1u) != 0u;   // corner x sits in upper half?
                f0[j] = hi ? make_float2(q.z, q.w) : make_float2(q.x, q.y);
                f1[j] = hi ? make_float2(q.x, q.y) : make_float2(q.z, q.w);
            }
        } else {
            const unsigned cx1 = cx + 1u;
#pragma unroll
            for (int j = 0; j < 4; j++) {
                const unsigned i0 = (cx  ^ s[j]) & m;
                const unsigned i1 = (cx1 ^ s[j]) & m;
                f0[j] = __ldg(&tab2[i0]);
                f1[j] = __ldg(&tab2[i1]);
            }
        }
        level_accumulate(l, f0, f1, fx, fy, fz, acc, sW0);
    }

    // ---- ReLU -> hidden to smem (transposed), reset accumulators ----
    {
        const int t = threadIdx.x;
#pragma unroll
        for (int j = 0; j < HID / 2; j++) {
            float a, b; upk2(acc[j], a, b);
            sH[(2 * j) * 128 + t]     = fmaxf(a, 0.0f);
            sH[(2 * j + 1) * 128 + t] = fmaxf(b, 0.0f);
            acc[j] = 0ull;
        }
    }

    // ---- layer 1: 64x64 ----
    {
        const int t = threadIdx.x;
#pragma unroll 8
        for (int i = 0; i < HID; i++) {
            const float hi = sH[i * 128 + t];
            const u64 ai = pk2(hi, hi);
            const ulonglong2* __restrict__ r = (const ulonglong2*)&sW1[i * HID];
#pragma unroll
            for (int j = 0; j < HID / 4; j++) {
                const ulonglong2 v = r[j];
                acc[2 * j]     = ffma2(ai, v.x, acc[2 * j]);
                acc[2 * j + 1] = ffma2(ai, v.y, acc[2 * j + 1]);
            }
        }
    }

    // ---- ReLU + layer 2 (64 -> 1) ----
    float res = 0.0f;
#pragma unroll
    for (int j = 0; j < HID / 2; j++) {
        float a, b; upk2(acc[j], a, b);
        res = fmaf(fmaxf(a, 0.0f), sW2[2 * j], res);
        res = fmaf(fmaxf(b, 0.0f), sW2[2 * j + 1], res);
    }
    out[pt] = res;
}

static LevelParams make_params(unsigned* qtotal_out) {
    LevelParams lp;
    unsigned qoff = 0;
    for (int l = 0; l < NLEV; l++) {
        const double r = floor(16.0 * pow(1.3819, (double)l));
        const int res = (int)r;
        lp.resf[l] = (float)res;
        const unsigned s1 = (unsigned)(res + 1);
        lp.s1[l] = s1;
        lp.s2[l] = s1 * s1;
        if (l < NDENSE) {
            // cover max idx0+1 = (res+1)^3 + (res+1)^2 + (res+1) + 1
            const unsigned cnt = s1 * s1 * s1 + s1 * s1 + s1 + 2u;
            lp.qoff[l] = qoff;
            lp.qcnt[l] = cnt;
            qoff += cnt;
        }
    }
    *qtotal_out = qoff;
    return lp;
}

extern "C" void kernel_launch(void* const* d_in, const int* in_sizes, int n_in,
                              void* d_out, int out_size) {
    const float* x      = (const float*)d_in[0];
    const float* tables = (const float*)d_in[1];
    const float* W0     = (const float*)d_in[2];
    const float* W1     = (const float*)d_in[3];
    const float* W2     = (const float*)d_in[4];
    float* out = (float*)d_out;

    const int npts = out_size;
    unsigned qtotal = 0;
    LevelParams lp = make_params(&qtotal);

    {
        const int bt = 256;
        const int bg = (int)((qtotal + bt - 1) / bt);
        build_q<<<bg, bt>>>((const float2*)tables, lp, qtotal);
    }

    const int block = 128;
    const int grid = (npts + block - 1) / block;
    sdf_fused<<<grid, block>>>(x, tables, W0, W1, W2, out, npts, lp);
}